// round 14
// baseline (speedup 1.0000x reference)
#include <cuda_runtime.h>
#include <cuda_bf16.h>
#include <cstdint>

#define DI __device__ __forceinline__

static constexpr int   NN     = 8192;
static constexpr int   DD     = 256;
static constexpr float EPS    = 1e-8f;
static constexpr float THR    = 1e-6f;
static constexpr float LN_EPS = 1e-5f;

// ---------------- device scratch ----------------
__device__ float          g_part[4 * NN];
__device__ float          g_inv[NN];
__device__ float          g_wsum[NN];
__device__ float          g_T[(size_t)NN * DD];
__device__ __nv_bfloat16  g_Tbf[(size_t)NN * DD];
__device__ __nv_bfloat16  g_Winb[DD * DD];
__device__ __nv_bfloat16  g_Woutb[DD * DD];
__device__ float          g_numA[(size_t)NN * DD];
__device__ float          g_numB[(size_t)NN * DD];
__device__ float          g_numC[(size_t)NN * DD];

// ---------------- helpers ----------------
DI uint32_t smem_u32(const void* p) {
    uint32_t a;
    asm("{ .reg .u64 t; cvta.to.shared.u64 t, %1; cvt.u32.u64 %0, t; }" : "=r"(a) : "l"(p));
    return a;
}
DI void ldsm4t(uint32_t* r, uint32_t addr) {
    asm volatile("ldmatrix.sync.aligned.m8n8.x4.trans.shared.b16 {%0,%1,%2,%3}, [%4];"
        : "=r"(r[0]), "=r"(r[1]), "=r"(r[2]), "=r"(r[3]) : "r"(addr));
}
DI void ldsm4(uint32_t* r, uint32_t addr) {
    asm volatile("ldmatrix.sync.aligned.m8n8.x4.shared.b16 {%0,%1,%2,%3}, [%4];"
        : "=r"(r[0]), "=r"(r[1]), "=r"(r[2]), "=r"(r[3]) : "r"(addr));
}
DI void mma_bf16(float* c, const uint32_t* a, const uint32_t* b) {
    asm volatile(
        "mma.sync.aligned.m16n8k16.row.col.f32.bf16.bf16.f32 "
        "{%0,%1,%2,%3}, {%4,%5,%6,%7}, {%8,%9}, {%0,%1,%2,%3};"
        : "+f"(c[0]), "+f"(c[1]), "+f"(c[2]), "+f"(c[3])
        : "r"(a[0]), "r"(a[1]), "r"(a[2]), "r"(a[3]), "r"(b[0]), "r"(b[1]));
}
DI uint32_t bf2u(float lo, float hi) {
    uint32_t r;
    asm("cvt.rn.bf16x2.f32 %0, %1, %2;" : "=r"(r) : "f"(hi), "f"(lo));
    return r;
}
DI uint4 cvt8bf(float4 a, float4 b) {
    uint4 u;
    u.x = bf2u(a.x, a.y); u.y = bf2u(a.z, a.w);
    u.z = bf2u(b.x, b.y); u.w = bf2u(b.z, b.w);
    return u;
}
DI void cp16(uint32_t smem_dst, const void* gptr) {
    asm volatile("cp.async.cg.shared.global [%0], [%1], 16;" :: "r"(smem_dst), "l"(gptr) : "memory");
}

// ================= kernel 1: column sums of M (4 row-quarters, 256 CTAs) =========
__global__ void colsum_kernel(const float* __restrict__ M) {
    __shared__ float red[8 * 128];
    int tid = threadIdx.x;
    int it = blockIdx.x >> 2, quart = blockIdx.x & 3;
    int i0 = it * 128;
    int rg = tid >> 5, i4 = (tid & 31) * 4;

    float a0 = 0.f, a1 = 0.f, a2 = 0.f, a3 = 0.f;
    int rbeg = quart * 2048 + rg, rend = quart * 2048 + 2048;
    for (int r = rbeg; r < rend; r += 32) {
        float4 m0 = *(const float4*)&M[(size_t)(r     ) * NN + i0 + i4];
        float4 m1 = *(const float4*)&M[(size_t)(r +  8) * NN + i0 + i4];
        float4 m2 = *(const float4*)&M[(size_t)(r + 16) * NN + i0 + i4];
        float4 m3 = *(const float4*)&M[(size_t)(r + 24) * NN + i0 + i4];
        a0 += m0.x + m1.x + m2.x + m3.x;
        a1 += m0.y + m1.y + m2.y + m3.y;
        a2 += m0.z + m1.z + m2.z + m3.z;
        a3 += m0.w + m1.w + m2.w + m3.w;
    }
    red[rg * 128 + i4 + 0] = a0; red[rg * 128 + i4 + 1] = a1;
    red[rg * 128 + i4 + 2] = a2; red[rg * 128 + i4 + 3] = a3;
    __syncthreads();
    if (tid < 128) {
        float s = 0.f;
#pragma unroll
        for (int g = 0; g < 8; g++) s += red[g * 128 + tid];
        g_part[quart * NN + i0 + tid] = s;
    }
}

// ================= kernel 2: prep =================
__global__ void prep_kernel(const float* __restrict__ W_in,
                            const float* __restrict__ W_out) {
    int gid = blockIdx.x * 256 + threadIdx.x;
    if (gid < NN) {
        float s = g_part[gid] + g_part[NN + gid] + g_part[2 * NN + gid] + g_part[3 * NN + gid];
        g_inv[gid]  = 1.f / (s + EPS);
        g_wsum[gid] = 0.f;
    }
    g_Winb[gid]  = __float2bfloat16(W_in[gid]);
    g_Woutb[gid] = __float2bfloat16(W_out[gid]);
}

// ================= kernel 3: T = X @ W_in + b_in =================
static constexpr int AP = 40;
static constexpr int BP = 136;

__global__ void __launch_bounds__(256, 1) t_kernel(const float* __restrict__ X,
                                                   const float* __restrict__ b_in) {
    __shared__ __nv_bfloat16 sA[2][128 * AP];
    __shared__ __nv_bfloat16 sB[2][32 * BP];

    int tid = threadIdx.x;
    int j0 = (blockIdx.x >> 1) * 128;
    int d0 = (blockIdx.x & 1) * 128;

    int xj = tid >> 1, xh = (tid & 1) * 16;
    int wk = tid >> 3, wd = (tid & 7) * 16;

    int w = tid >> 5, lane = tid & 31;
    int iw = (w & 3) * 32, dw = (w >> 2) * 64;
    int q = lane >> 3, r7 = lane & 7;
    int l15 = lane & 15, lh = (lane >> 4) * 8;

    float acc[2][8][4] = {};
    float4 xr[4];
    uint4  wr[2];

#pragma unroll
    for (int p = 0; p < 4; p++)
        xr[p] = *(const float4*)&X[(size_t)(j0 + xj) * DD + xh + p * 4];
#pragma unroll
    for (int p = 0; p < 2; p++)
        wr[p] = *(const uint4*)&g_Winb[(size_t)wk * DD + d0 + wd + p * 8];

    *(uint4*)&sA[0][xj * AP + xh]     = cvt8bf(xr[0], xr[1]);
    *(uint4*)&sA[0][xj * AP + xh + 8] = cvt8bf(xr[2], xr[3]);
    *(uint4*)&sB[0][wk * BP + wd]     = wr[0];
    *(uint4*)&sB[0][wk * BP + wd + 8] = wr[1];
    __syncthreads();

    const int NCk = DD / 32;
    int buf = 0;
    for (int c = 0; c < NCk; c++) {
        int nbuf = buf ^ 1;
        if (c + 1 < NCk) {
            int k0 = (c + 1) * 32;
#pragma unroll
            for (int p = 0; p < 4; p++)
                xr[p] = *(const float4*)&X[(size_t)(j0 + xj) * DD + k0 + xh + p * 4];
#pragma unroll
            for (int p = 0; p < 2; p++)
                wr[p] = *(const uint4*)&g_Winb[(size_t)(k0 + wk) * DD + d0 + wd + p * 8];
        }
        uint32_t swb = smem_u32(sA[buf]), stb = smem_u32(sB[buf]);
#pragma unroll
        for (int kk = 0; kk < 32; kk += 16) {
            uint32_t a[2][4];
#pragma unroll
            for (int mb = 0; mb < 2; mb++)
                ldsm4(a[mb], swb + (uint32_t)(((iw + mb * 16 + l15) * AP + kk + lh) * 2));
#pragma unroll
            for (int nbp = 0; nbp < 4; nbp++) {
                uint32_t b[4];
                ldsm4t(b, stb + (uint32_t)(((kk + (q & 1) * 8 + r7) * BP + dw + (nbp * 2 + (q >> 1)) * 8) * 2));
                mma_bf16(acc[0][2 * nbp],     a[0], b);
                mma_bf16(acc[1][2 * nbp],     a[1], b);
                mma_bf16(acc[0][2 * nbp + 1], a[0], b + 2);
                mma_bf16(acc[1][2 * nbp + 1], a[1], b + 2);
            }
        }
        if (c + 1 < NCk) {
            *(uint4*)&sA[nbuf][xj * AP + xh]     = cvt8bf(xr[0], xr[1]);
            *(uint4*)&sA[nbuf][xj * AP + xh + 8] = cvt8bf(xr[2], xr[3]);
            *(uint4*)&sB[nbuf][wk * BP + wd]     = wr[0];
            *(uint4*)&sB[nbuf][wk * BP + wd + 8] = wr[1];
        }
        __syncthreads();
        buf = nbuf;
    }

    int gi = lane >> 2, gk = (lane & 3) * 2;
#pragma unroll
    for (int mb = 0; mb < 2; mb++)
#pragma unroll
        for (int nb = 0; nb < 8; nb++) {
            int dg = d0 + dw + nb * 8 + gk;
            float2 b2 = *(const float2*)&b_in[dg];
            float v0 = acc[mb][nb][0] + b2.x, v1 = acc[mb][nb][1] + b2.y;
            float v2 = acc[mb][nb][2] + b2.x, v3 = acc[mb][nb][3] + b2.y;
            size_t r0 = (size_t)(j0 + iw + mb * 16 + gi) * DD + dg;
            *(float2*)&g_T[r0]          = make_float2(v0, v1);
            *(float2*)&g_T[r0 + 8 * DD] = make_float2(v2, v3);
            *(uint32_t*)&g_Tbf[r0]          = bf2u(v0, v1);
            *(uint32_t*)&g_Tbf[r0 + 8 * DD] = bf2u(v2, v3);
        }
}

// ================= kernel 4: big GEMM (296 CTAs, 2/SM, cp.async distance-2) ======
static constexpr int PITCH = 136;
static constexpr uint32_t MRAW_B = 32u * 128u * 4u;      // 16384 raw fp32 M tile
static constexpr uint32_t SWB2   = 32u * PITCH * 2u;     // 8704 bf16 tile
static constexpr uint32_t SMEM_DYN = 3 * MRAW_B + 2 * SWB2 + 3 * SWB2;  // 92672

__global__ void __launch_bounds__(256, 2) mma_kernel(const float* __restrict__ M) {
    extern __shared__ char ds[];
    float* Mraw[3] = { (float*)ds, (float*)(ds + MRAW_B), (float*)(ds + 2 * MRAW_B) };
    __nv_bfloat16* sW[2] = { (__nv_bfloat16*)(ds + 3 * MRAW_B),
                             (__nv_bfloat16*)(ds + 3 * MRAW_B + SWB2) };
    __nv_bfloat16* sT[3] = { (__nv_bfloat16*)(ds + 3 * MRAW_B + 2 * SWB2),
                             (__nv_bfloat16*)(ds + 3 * MRAW_B + 3 * SWB2),
                             (__nv_bfloat16*)(ds + 3 * MRAW_B + 4 * SWB2) };

    int tid = threadIdx.x;
    int bid = blockIdx.x;
    // 128 tiles; tiles 0..39 -> 3 pieces (86/85/85 chunks), 40..127 -> 2 (128/128)
    int tile, part, nparts, cbeg, NC;
    if (bid < 120) {
        tile = bid / 3; part = bid % 3; nparts = 3;
        cbeg = (part == 0) ? 0 : (86 + 85 * (part - 1));
        NC   = (part == 0) ? 86 : 85;
    } else {
        int b2 = bid - 120;
        tile = 40 + (b2 >> 1); part = b2 & 1; nparts = 2;
        cbeg = part * 128; NC = 128;
    }
    int it = tile >> 1, dt = tile & 1;
    int i0 = it * 128, d0 = dt * 128;

    int cj = tid >> 5;
    int ci = (tid & 31) * 4;
    float4 inv4 = *(const float4*)&g_inv[i0 + ci];
    float wa0 = 0.f, wa1 = 0.f, wa2 = 0.f, wa3 = 0.f;

    int tj = tid >> 4;
    int tc = (tid & 15) * 8;

    int w = tid >> 5, lane = tid & 31;
    int iw = (w & 3) * 32, dw = (w >> 2) * 64;
    int q  = lane >> 3, r7 = lane & 7;

    float acc[2][8][4] = {};

    const float*          Mb = M     + (size_t)cbeg * 32 * NN;
    const __nv_bfloat16*  Tb = g_Tbf + (size_t)cbeg * 32 * DD;

    auto ISSUE = [&](int c) {
        int r = c % 3;
        size_t jb = (size_t)c * 32;
        uint32_t mdst = smem_u32(Mraw[r]);
#pragma unroll
        for (int jj = 0; jj < 4; jj++) {
            int j = cj + jj * 8;
            cp16(mdst + (uint32_t)(j * 128 + ci) * 4, &Mb[(jb + j) * NN + i0 + ci]);
        }
        uint32_t tdst = smem_u32(sT[r]);
#pragma unroll
        for (int jj = 0; jj < 2; jj++) {
            int j = tj + jj * 16;
            cp16(tdst + (uint32_t)(j * PITCH + tc) * 2, &Tb[(jb + j) * DD + d0 + tc]);
        }
        asm volatile("cp.async.commit_group;" ::: "memory");
    };
    auto CONVERT = [&](int c) {
        const float* mr_ = Mraw[c % 3];
        __nv_bfloat16* w_ = sW[c & 1];
#pragma unroll
        for (int jj = 0; jj < 4; jj++) {
            int j = cj + jj * 8;
            float4 m4 = *(const float4*)&mr_[j * 128 + ci];
            float w0 = m4.x * inv4.x; w0 = (w0 > THR) ? w0 : 0.f;
            float w1 = m4.y * inv4.y; w1 = (w1 > THR) ? w1 : 0.f;
            float w2 = m4.z * inv4.z; w2 = (w2 > THR) ? w2 : 0.f;
            float w3 = m4.w * inv4.w; w3 = (w3 > THR) ? w3 : 0.f;
            if (dt == 0) { wa0 += w0; wa1 += w1; wa2 += w2; wa3 += w3; }
            uint2 v; v.x = bf2u(w0, w1); v.y = bf2u(w2, w3);
            *(uint2*)&w_[j * PITCH + ci] = v;
        }
    };

    // prologue: groups 0,1 in flight; convert chunk 0
    ISSUE(0);
    ISSUE(1);
    asm volatile("cp.async.wait_group 1;" ::: "memory");
    __syncthreads();
    CONVERT(0);
    __syncthreads();

    for (int c = 0; c < NC; c++) {
        // ---- MMA on sW[c&1], sT[c%3] ----
        uint32_t swb = smem_u32(sW[c & 1]), stb = smem_u32(sT[c % 3]);
#pragma unroll
        for (int kk = 0; kk < 32; kk += 16) {
            uint32_t a[2][4];
#pragma unroll
            for (int mb = 0; mb < 2; mb++)
                ldsm4t(a[mb], swb + (uint32_t)(((kk + (q >> 1) * 8 + r7) * PITCH + iw + mb * 16 + (q & 1) * 8) * 2));
#pragma unroll
            for (int nbp = 0; nbp < 4; nbp++) {
                uint32_t b[4];
                ldsm4t(b, stb + (uint32_t)(((kk + (q & 1) * 8 + r7) * PITCH + dw + (nbp * 2 + (q >> 1)) * 8) * 2));
                mma_bf16(acc[0][2 * nbp],     a[0], b);
                mma_bf16(acc[1][2 * nbp],     a[1], b);
                mma_bf16(acc[0][2 * nbp + 1], a[0], b + 2);
                mma_bf16(acc[1][2 * nbp + 1], a[1], b + 2);
            }
        }

        if (c + 2 < NC) ISSUE(c + 2);
        if (c + 1 < NC) {
            if (c + 2 < NC) { asm volatile("cp.async.wait_group 1;" ::: "memory"); }
            else            { asm volatile("cp.async.wait_group 0;" ::: "memory"); }
            CONVERT(c + 1);
        }
        __syncthreads();
    }

    if (dt == 0) {
        atomicAdd(&g_wsum[i0 + ci + 0], wa0);
        atomicAdd(&g_wsum[i0 + ci + 1], wa1);
        atomicAdd(&g_wsum[i0 + ci + 2], wa2);
        atomicAdd(&g_wsum[i0 + ci + 3], wa3);
    }

    float* numOut = (part == 0) ? g_numA : (part == 1) ? g_numB : g_numC;
    int gi = lane >> 2, gk = (lane & 3) * 2;
#pragma unroll
    for (int mb = 0; mb < 2; mb++)
#pragma unroll
        for (int nb = 0; nb < 8; nb++) {
            int i = i0 + iw + mb * 16 + gi;
            int d = d0 + dw + nb * 8 + gk;
            float* p = &numOut[(size_t)i * DD + d];
            p[0]          = acc[mb][nb][0];
            p[1]          = acc[mb][nb][1];
            p[8 * DD]     = acc[mb][nb][2];
            p[8 * DD + 1] = acc[mb][nb][3];
        }

    if (nparts == 2 && part == 0) {
        for (int idx = tid; idx < 128 * 32; idx += 256) {
            int r = idx >> 5, c4 = (idx & 31) * 4;
            *(float4*)&g_numC[(size_t)(i0 + r) * DD + d0 + c4] = make_float4(0.f, 0.f, 0.f, 0.f);
        }
    }
}

// ================= kernel 5: epilogue =================
static constexpr int EBP = 264;

__global__ void __launch_bounds__(256, 1) epi_kernel(const float* __restrict__ X,
                                                     const float* __restrict__ b_out,
                                                     const float* __restrict__ ln_s,
                                                     const float* __restrict__ ln_b,
                                                     float* __restrict__ out) {
    __shared__ __nv_bfloat16 sA[2][64 * AP];
    __shared__ __nv_bfloat16 sB[2][32 * EBP];
    __shared__ float2 red[64][2];
    __shared__ float  winv_s[64];
    __shared__ int    flag_s[64];

    int tid = threadIdx.x;
    int i0  = blockIdx.x * 64;

    if (tid < 64) {
        float ws = g_wsum[i0 + tid];
        winv_s[tid] = 1.f / (ws + EPS);
        flag_s[tid] = (ws > 0.f) ? 1 : 0;
    }
    __syncthreads();

    int ar = tid >> 2, ac = (tid & 3) * 8;
    float wv = winv_s[ar];
    int   fl = flag_s[ar];
    int wk = tid >> 3, wd = (tid & 7) * 32;

    int w = tid >> 5, lane = tid & 31;
    int iwp = (w & 3) * 16, dwp = (w >> 2) * 128;
    int q  = lane >> 3, r7 = lane & 7;
    int l15 = lane & 15, lh = (lane >> 4) * 8;

    float acc[16][4] = {};
    float4 av[2];
    uint4  wr[4];

    auto loadA = [&](int k0, float4* v) {
        size_t base = (size_t)(i0 + ar) * DD + k0 + ac;
        if (fl) {
#pragma unroll
            for (int p = 0; p < 2; p++) {
                float4 a4 = *(const float4*)&g_numA[base + p * 4];
                float4 b4 = *(const float4*)&g_numB[base + p * 4];
                float4 c4 = *(const float4*)&g_numC[base + p * 4];
                v[p] = make_float4((a4.x + b4.x + c4.x) * wv, (a4.y + b4.y + c4.y) * wv,
                                   (a4.z + b4.z + c4.z) * wv, (a4.w + b4.w + c4.w) * wv);
            }
        } else {
#pragma unroll
            for (int p = 0; p < 2; p++) v[p] = *(const float4*)&g_T[base + p * 4];
        }
    };

    loadA(0, av);
#pragma unroll
    for (int p = 0; p < 4; p++)
        wr[p] = *(const uint4*)&g_Woutb[(size_t)wk * DD + wd + p * 8];

    *(uint4*)&sA[0][ar * AP + ac] = cvt8bf(av[0], av[1]);
#pragma unroll
    for (int p = 0; p < 4; p++) *(uint4*)&sB[0][wk * EBP + wd + p * 8] = wr[p];
    __syncthreads();

    const int NCk = DD / 32;
    int buf = 0;
    for (int c = 0; c < NCk; c++) {
        int nbuf = buf ^ 1;
        if (c + 1 < NCk) {
            int k0 = (c + 1) * 32;
            loadA(k0, av);
#pragma unroll
            for (int p = 0; p < 4; p++)
                wr[p] = *(const uint4*)&g_Woutb[(size_t)(k0 + wk) * DD + wd + p * 8];
        }
        uint32_t swb = smem_u32(sA[buf]), stb = smem_u32(sB[buf]);
#pragma unroll
        for (int kk = 0; kk < 32; kk += 16) {
            uint32_t a[4];
            ldsm4(a, swb + (uint32_t)(((iwp + l15) * AP + kk + lh) * 2));
#pragma unroll
            for (int nbp = 0; nbp < 8; nbp++) {
                uint32_t b[4];
                ldsm4t(b, stb + (uint32_t)(((kk + (q & 1) * 8 + r7) * EBP + dwp + (nbp * 2 + (q >> 1)) * 8) * 2));
                mma_bf16(acc[2 * nbp],     a, b);
                mma_bf16(acc[2 * nbp + 1], a, b + 2);
            }
        }
        if (c + 1 < NCk) {
            *(uint4*)&sA[nbuf][ar * AP + ac] = cvt8bf(av[0], av[1]);
#pragma unroll
            for (int p = 0; p < 4; p++) *(uint4*)&sB[nbuf][wk * EBP + wd + p * 8] = wr[p];
        }
        __syncthreads();
        buf = nbuf;
    }

    int gi = lane >> 2, gk = (lane & 3) * 2;
    int r0 = iwp + gi, r1 = r0 + 8;
    float s0 = 0.f, q0 = 0.f, s1 = 0.f, q1 = 0.f;
#pragma unroll
    for (int nb = 0; nb < 16; nb++) {
        int d = dwp + nb * 8 + gk;
        float2 b2 = *(const float2*)&b_out[d];
        float2 x0 = *(const float2*)&X[(size_t)(i0 + r0) * DD + d];
        float2 x1 = *(const float2*)&X[(size_t)(i0 + r1) * DD + d];
        acc[nb][0] += b2.x + x0.x; acc[nb][1] += b2.y + x0.y;
        acc[nb][2] += b2.x + x1.x; acc[nb][3] += b2.y + x1.y;
        s0 += acc[nb][0] + acc[nb][1]; q0 += acc[nb][0] * acc[nb][0] + acc[nb][1] * acc[nb][1];
        s1 += acc[nb][2] + acc[nb][3]; q1 += acc[nb][2] * acc[nb][2] + acc[nb][3] * acc[nb][3];
    }
#pragma unroll
    for (int o = 1; o <= 2; o <<= 1) {
        s0 += __shfl_xor_sync(0xFFFFFFFFu, s0, o);
        q0 += __shfl_xor_sync(0xFFFFFFFFu, q0, o);
        s1 += __shfl_xor_sync(0xFFFFFFFFu, s1, o);
        q1 += __shfl_xor_sync(0xFFFFFFFFu, q1, o);
    }
    int dwi = w >> 2;
    if (gk == 0) {
        red[r0][dwi] = make_float2(s0, q0);
        red[r1][dwi] = make_float2(s1, q1);
    }
    __syncthreads();
    float2 ra0 = red[r0][0], rb0 = red[r0][1];
    float2 ra1 = red[r1][0], rb1 = red[r1][1];
    float mu0 = (ra0.x + rb0.x) * (1.f / 256.f);
    float mu1 = (ra1.x + rb1.x) * (1.f / 256.f);
    float v0  = (ra0.y + rb0.y) * (1.f / 256.f) - mu0 * mu0;
    float v1  = (ra1.y + rb1.y) * (1.f / 256.f) - mu1 * mu1;
    float rs0 = rsqrtf(v0 + LN_EPS), rs1 = rsqrtf(v1 + LN_EPS);
#pragma unroll
    for (int nb = 0; nb < 16; nb++) {
        int d = dwp + nb * 8 + gk;
        float2 ls = *(const float2*)&ln_s[d];
        float2 lb = *(const float2*)&ln_b[d];
        *(float2*)&out[(size_t)(i0 + r0) * DD + d] =
            make_float2((acc[nb][0] - mu0) * rs0 * ls.x + lb.x,
                        (acc[nb][1] - mu0) * rs0 * ls.y + lb.y);
        *(float2*)&out[(size_t)(i0 + r1) * DD + d] =
            make_float2((acc[nb][2] - mu1) * rs1 * ls.x + lb.x,
                        (acc[nb][3] - mu1) * rs1 * ls.y + lb.y);
    }
}

// ================= launch =================
extern "C" void kernel_launch(void* const* d_in, const int* in_sizes, int n_in,
                              void* d_out, int out_size) {
    const float* X     = (const float*)d_in[0];
    const float* M     = (const float*)d_in[1];
    const float* W_in  = (const float*)d_in[2];
    const float* b_in  = (const float*)d_in[3];
    const float* W_out = (const float*)d_in[4];
    const float* b_out = (const float*)d_in[5];
    const float* ln_s  = (const float*)d_in[6];
    const float* ln_b  = (const float*)d_in[7];
    float* out = (float*)d_out;

    cudaFuncSetAttribute(mma_kernel, cudaFuncAttributeMaxDynamicSharedMemorySize, SMEM_DYN);

    colsum_kernel<<<256, 256>>>(M);
    prep_kernel  <<<256, 256>>>(W_in, W_out);
    t_kernel     <<<128, 256>>>(X, b_in);
    mma_kernel   <<<296, 256, SMEM_DYN>>>(M);
    epi_kernel   <<<128, 256>>>(X, b_out, ln_s, ln_b, out);
}

// round 15
// speedup vs baseline: 1.1213x; 1.1213x over previous
#include <cuda_runtime.h>
#include <cuda_bf16.h>
#include <cstdint>

#define DI __device__ __forceinline__

static constexpr int   NN     = 8192;
static constexpr int   DD     = 256;
static constexpr float EPS    = 1e-8f;
static constexpr float THR    = 1e-6f;
static constexpr float LN_EPS = 1e-5f;

// ---------------- device scratch ----------------
__device__ float          g_part[4 * NN];
__device__ float          g_inv[NN];
__device__ float          g_wsum[NN];
__device__ float          g_T[(size_t)NN * DD];
__device__ __nv_bfloat16  g_Tbf[(size_t)NN * DD];
__device__ __nv_bfloat16  g_Winb[DD * DD];
__device__ __nv_bfloat16  g_Woutb[DD * DD];
__device__ float          g_numA[(size_t)NN * DD];
__device__ float          g_numB[(size_t)NN * DD];
__device__ float          g_numC[(size_t)NN * DD];

// ---------------- helpers ----------------
DI uint32_t smem_u32(const void* p) {
    uint32_t a;
    asm("{ .reg .u64 t; cvta.to.shared.u64 t, %1; cvt.u32.u64 %0, t; }" : "=r"(a) : "l"(p));
    return a;
}
DI void ldsm4t(uint32_t* r, uint32_t addr) {
    asm volatile("ldmatrix.sync.aligned.m8n8.x4.trans.shared.b16 {%0,%1,%2,%3}, [%4];"
        : "=r"(r[0]), "=r"(r[1]), "=r"(r[2]), "=r"(r[3]) : "r"(addr));
}
DI void ldsm4(uint32_t* r, uint32_t addr) {
    asm volatile("ldmatrix.sync.aligned.m8n8.x4.shared.b16 {%0,%1,%2,%3}, [%4];"
        : "=r"(r[0]), "=r"(r[1]), "=r"(r[2]), "=r"(r[3]) : "r"(addr));
}
DI void mma_bf16(float* c, const uint32_t* a, const uint32_t* b) {
    asm volatile(
        "mma.sync.aligned.m16n8k16.row.col.f32.bf16.bf16.f32 "
        "{%0,%1,%2,%3}, {%4,%5,%6,%7}, {%8,%9}, {%0,%1,%2,%3};"
        : "+f"(c[0]), "+f"(c[1]), "+f"(c[2]), "+f"(c[3])
        : "r"(a[0]), "r"(a[1]), "r"(a[2]), "r"(a[3]), "r"(b[0]), "r"(b[1]));
}
DI uint32_t bf2u(float lo, float hi) {
    uint32_t r;
    asm("cvt.rn.bf16x2.f32 %0, %1, %2;" : "=r"(r) : "f"(hi), "f"(lo));
    return r;
}
DI uint4 cvt8bf(float4 a, float4 b) {
    uint4 u;
    u.x = bf2u(a.x, a.y); u.y = bf2u(a.z, a.w);
    u.z = bf2u(b.x, b.y); u.w = bf2u(b.z, b.w);
    return u;
}

// ================= kernel 1: FUSED colsum (bid<256) + T GEMM (bid>=256) =========
static constexpr int AP = 40;
static constexpr int BP = 136;
// t-branch smem: 2*128*AP + 2*32*BP bf16 = 20480 + 17408 = 37888 B (covers colsum's 4KB)
static constexpr uint32_t PRE_SMEM = 2u * 128u * AP * 2u + 2u * 32u * BP * 2u;

__global__ void __launch_bounds__(256) pre_kernel(const float* __restrict__ M,
                                                  const float* __restrict__ X,
                                                  const float* __restrict__ b_in) {
    extern __shared__ char ps[];
    int tid = threadIdx.x;

    if (blockIdx.x < 256) {
        // ---------------- colsum branch (4 row-quarters per i-tile) ----------------
        float* red = (float*)ps;                      // 8*128 floats
        int it = blockIdx.x >> 2, quart = blockIdx.x & 3;
        int i0 = it * 128;
        int rg = tid >> 5, i4 = (tid & 31) * 4;

        float a0 = 0.f, a1 = 0.f, a2 = 0.f, a3 = 0.f;
        int rbeg = quart * 2048 + rg, rend = quart * 2048 + 2048;
        for (int r = rbeg; r < rend; r += 32) {
            float4 m0 = *(const float4*)&M[(size_t)(r     ) * NN + i0 + i4];
            float4 m1 = *(const float4*)&M[(size_t)(r +  8) * NN + i0 + i4];
            float4 m2 = *(const float4*)&M[(size_t)(r + 16) * NN + i0 + i4];
            float4 m3 = *(const float4*)&M[(size_t)(r + 24) * NN + i0 + i4];
            a0 += m0.x + m1.x + m2.x + m3.x;
            a1 += m0.y + m1.y + m2.y + m3.y;
            a2 += m0.z + m1.z + m2.z + m3.z;
            a3 += m0.w + m1.w + m2.w + m3.w;
        }
        red[rg * 128 + i4 + 0] = a0; red[rg * 128 + i4 + 1] = a1;
        red[rg * 128 + i4 + 2] = a2; red[rg * 128 + i4 + 3] = a3;
        __syncthreads();
        if (tid < 128) {
            float s = 0.f;
#pragma unroll
            for (int g = 0; g < 8; g++) s += red[g * 128 + tid];
            g_part[quart * NN + i0 + tid] = s;
        }
        return;
    }

    // ---------------- T = X @ W_in + b_in branch ----------------
    int bid = blockIdx.x - 256;                       // 0..127
    __nv_bfloat16* sA0 = (__nv_bfloat16*)ps;                          // 128*AP
    __nv_bfloat16* sA1 = sA0 + 128 * AP;
    __nv_bfloat16* sB0 = sA1 + 128 * AP;                              // 32*BP
    __nv_bfloat16* sB1 = sB0 + 32 * BP;
    __nv_bfloat16* sAb[2] = { sA0, sA1 };
    __nv_bfloat16* sBb[2] = { sB0, sB1 };

    int j0 = (bid >> 1) * 128;
    int d0 = (bid & 1) * 128;

    int xj = tid >> 1, xh = (tid & 1) * 16;
    int wk = tid >> 3, wd = (tid & 7) * 16;

    int w = tid >> 5, lane = tid & 31;
    int iw = (w & 3) * 32, dw = (w >> 2) * 64;
    int q = lane >> 3, r7 = lane & 7;
    int l15 = lane & 15, lh = (lane >> 4) * 8;

    float acc[2][8][4] = {};
    float4 xr[4];
    uint4  wr[2];

#pragma unroll
    for (int p = 0; p < 4; p++)
        xr[p] = *(const float4*)&X[(size_t)(j0 + xj) * DD + xh + p * 4];
#pragma unroll
    for (int p = 0; p < 2; p++)
        wr[p] = *(const uint4*)&g_Winb[(size_t)wk * DD + d0 + wd + p * 8];

    *(uint4*)&sAb[0][xj * AP + xh]     = cvt8bf(xr[0], xr[1]);
    *(uint4*)&sAb[0][xj * AP + xh + 8] = cvt8bf(xr[2], xr[3]);
    *(uint4*)&sBb[0][wk * BP + wd]     = wr[0];
    *(uint4*)&sBb[0][wk * BP + wd + 8] = wr[1];
    __syncthreads();

    const int NCk = DD / 32;
    int buf = 0;
    for (int c = 0; c < NCk; c++) {
        int nbuf = buf ^ 1;
        if (c + 1 < NCk) {
            int k0 = (c + 1) * 32;
#pragma unroll
            for (int p = 0; p < 4; p++)
                xr[p] = *(const float4*)&X[(size_t)(j0 + xj) * DD + k0 + xh + p * 4];
#pragma unroll
            for (int p = 0; p < 2; p++)
                wr[p] = *(const uint4*)&g_Winb[(size_t)(k0 + wk) * DD + d0 + wd + p * 8];
        }
        uint32_t swb = smem_u32(sAb[buf]), stb = smem_u32(sBb[buf]);
#pragma unroll
        for (int kk = 0; kk < 32; kk += 16) {
            uint32_t a[2][4];
#pragma unroll
            for (int mb = 0; mb < 2; mb++)
                ldsm4(a[mb], swb + (uint32_t)(((iw + mb * 16 + l15) * AP + kk + lh) * 2));
#pragma unroll
            for (int nbp = 0; nbp < 4; nbp++) {
                uint32_t b[4];
                ldsm4t(b, stb + (uint32_t)(((kk + (q & 1) * 8 + r7) * BP + dw + (nbp * 2 + (q >> 1)) * 8) * 2));
                mma_bf16(acc[0][2 * nbp],     a[0], b);
                mma_bf16(acc[1][2 * nbp],     a[1], b);
                mma_bf16(acc[0][2 * nbp + 1], a[0], b + 2);
                mma_bf16(acc[1][2 * nbp + 1], a[1], b + 2);
            }
        }
        if (c + 1 < NCk) {
            *(uint4*)&sAb[nbuf][xj * AP + xh]     = cvt8bf(xr[0], xr[1]);
            *(uint4*)&sAb[nbuf][xj * AP + xh + 8] = cvt8bf(xr[2], xr[3]);
            *(uint4*)&sBb[nbuf][wk * BP + wd]     = wr[0];
            *(uint4*)&sBb[nbuf][wk * BP + wd + 8] = wr[1];
        }
        __syncthreads();
        buf = nbuf;
    }

    int gi = lane >> 2, gk = (lane & 3) * 2;
#pragma unroll
    for (int mb = 0; mb < 2; mb++)
#pragma unroll
        for (int nb = 0; nb < 8; nb++) {
            int dg = d0 + dw + nb * 8 + gk;
            float2 b2 = *(const float2*)&b_in[dg];
            float v0 = acc[mb][nb][0] + b2.x, v1 = acc[mb][nb][1] + b2.y;
            float v2 = acc[mb][nb][2] + b2.x, v3 = acc[mb][nb][3] + b2.y;
            size_t r0 = (size_t)(j0 + iw + mb * 16 + gi) * DD + dg;
            *(float2*)&g_T[r0]          = make_float2(v0, v1);
            *(float2*)&g_T[r0 + 8 * DD] = make_float2(v2, v3);
            *(uint32_t*)&g_Tbf[r0]          = bf2u(v0, v1);
            *(uint32_t*)&g_Tbf[r0 + 8 * DD] = bf2u(v2, v3);
        }
}

// ================= kernel 2: prep =================
__global__ void prep_kernel(const float* __restrict__ W_in,
                            const float* __restrict__ W_out) {
    int gid = blockIdx.x * 256 + threadIdx.x;
    if (gid < NN) {
        float s = g_part[gid] + g_part[NN + gid] + g_part[2 * NN + gid] + g_part[3 * NN + gid];
        g_inv[gid]  = 1.f / (s + EPS);
        g_wsum[gid] = 0.f;
    }
    g_Winb[gid]  = __float2bfloat16(W_in[gid]);
    g_Woutb[gid] = __float2bfloat16(W_out[gid]);
}

// prep0: W->bf16 only (must run BEFORE pre_kernel's t-branch reads g_Winb)
__global__ void prep0_kernel(const float* __restrict__ W_in,
                             const float* __restrict__ W_out) {
    int gid = blockIdx.x * 256 + threadIdx.x;
    g_Winb[gid]  = __float2bfloat16(W_in[gid]);
    g_Woutb[gid] = __float2bfloat16(W_out[gid]);
}
// prep1: inv/wsum only (after colsum)
__global__ void prep1_kernel() {
    int gid = blockIdx.x * 256 + threadIdx.x;
    float s = g_part[gid] + g_part[NN + gid] + g_part[2 * NN + gid] + g_part[3 * NN + gid];
    g_inv[gid]  = 1.f / (s + EPS);
    g_wsum[gid] = 0.f;
}

// ================= kernel 4: big GEMM (R13/R9 design: 296 CTAs, 2/SM) ====
static constexpr int PITCH = 136;

__global__ void __launch_bounds__(256, 2) mma_kernel(const float* __restrict__ M) {
    __shared__ __nv_bfloat16 sW[2][32 * PITCH];
    __shared__ __nv_bfloat16 sT[2][32 * PITCH];

    int tid = threadIdx.x;
    int bid = blockIdx.x;
    int tile, part, nparts, cbeg, NC;
    if (bid < 120) {
        tile = bid / 3; part = bid % 3; nparts = 3;
        cbeg = (part == 0) ? 0 : (86 + 85 * (part - 1));
        NC   = (part == 0) ? 86 : 85;
    } else {
        int b2 = bid - 120;
        tile = 40 + (b2 >> 1); part = b2 & 1; nparts = 2;
        cbeg = part * 128; NC = 128;
    }
    int it = tile >> 1, dt = tile & 1;
    int i0 = it * 128, d0 = dt * 128;

    int cj = tid >> 5;
    int ci = (tid & 31) * 4;
    float4 inv4 = *(const float4*)&g_inv[i0 + ci];
    float wa0 = 0.f, wa1 = 0.f, wa2 = 0.f, wa3 = 0.f;

    int tj = tid >> 4;
    int tc = (tid & 15) * 8;

    int w = tid >> 5, lane = tid & 31;
    int iw = (w & 3) * 32, dw = (w >> 2) * 64;
    int q  = lane >> 3, r7 = lane & 7;

    float acc[2][8][4] = {};

    const float*          Mb = M     + (size_t)cbeg * 32 * NN;
    const __nv_bfloat16*  Tb = g_Tbf + (size_t)cbeg * 32 * DD;

    float4 mr[4], tr[2];
#pragma unroll
    for (int jj = 0; jj < 4; jj++)
        mr[jj] = *(const float4*)&Mb[(size_t)(cj + jj * 8) * NN + i0 + ci];
#pragma unroll
    for (int jj = 0; jj < 2; jj++)
        tr[jj] = *(const float4*)&Tb[(size_t)(tj + jj * 16) * DD + d0 + tc];

#pragma unroll
    for (int jj = 0; jj < 4; jj++) {
        int j = cj + jj * 8;
        float w0 = mr[jj].x * inv4.x; w0 = (w0 > THR) ? w0 : 0.f;
        float w1 = mr[jj].y * inv4.y; w1 = (w1 > THR) ? w1 : 0.f;
        float w2 = mr[jj].z * inv4.z; w2 = (w2 > THR) ? w2 : 0.f;
        float w3 = mr[jj].w * inv4.w; w3 = (w3 > THR) ? w3 : 0.f;
        if (dt == 0) { wa0 += w0; wa1 += w1; wa2 += w2; wa3 += w3; }
        *(uint32_t*)&sW[0][j * PITCH + ci]     = bf2u(w0, w1);
        *(uint32_t*)&sW[0][j * PITCH + ci + 2] = bf2u(w2, w3);
    }
#pragma unroll
    for (int jj = 0; jj < 2; jj++)
        *(float4*)&sT[0][(tj + jj * 16) * PITCH + tc] = tr[jj];
    __syncthreads();

    int buf = 0;
    for (int c = 0; c < NC; c++) {
        int nbuf = buf ^ 1;
        if (c + 1 < NC) {
            size_t koff = (size_t)(c + 1) * 32;
#pragma unroll
            for (int jj = 0; jj < 4; jj++)
                mr[jj] = *(const float4*)&Mb[(koff + cj + jj * 8) * NN + i0 + ci];
#pragma unroll
            for (int jj = 0; jj < 2; jj++)
                tr[jj] = *(const float4*)&Tb[(koff + tj + jj * 16) * DD + d0 + tc];
        }

        uint32_t swb = smem_u32(sW[buf]), stb = smem_u32(sT[buf]);
#pragma unroll
        for (int kk = 0; kk < 32; kk += 16) {
            uint32_t a[2][4];
#pragma unroll
            for (int mb = 0; mb < 2; mb++)
                ldsm4t(a[mb], swb + (uint32_t)(((kk + (q >> 1) * 8 + r7) * PITCH + iw + mb * 16 + (q & 1) * 8) * 2));
#pragma unroll
            for (int nbp = 0; nbp < 4; nbp++) {
                uint32_t b[4];
                ldsm4t(b, stb + (uint32_t)(((kk + (q & 1) * 8 + r7) * PITCH + dw + (nbp * 2 + (q >> 1)) * 8) * 2));
                mma_bf16(acc[0][2 * nbp],     a[0], b);
                mma_bf16(acc[1][2 * nbp],     a[1], b);
                mma_bf16(acc[0][2 * nbp + 1], a[0], b + 2);
                mma_bf16(acc[1][2 * nbp + 1], a[1], b + 2);
            }
        }

        if (c + 1 < NC) {
#pragma unroll
            for (int jj = 0; jj < 4; jj++) {
                int j = cj + jj * 8;
                float w0 = mr[jj].x * inv4.x; w0 = (w0 > THR) ? w0 : 0.f;
                float w1 = mr[jj].y * inv4.y; w1 = (w1 > THR) ? w1 : 0.f;
                float w2 = mr[jj].z * inv4.z; w2 = (w2 > THR) ? w2 : 0.f;
                float w3 = mr[jj].w * inv4.w; w3 = (w3 > THR) ? w3 : 0.f;
                if (dt == 0) { wa0 += w0; wa1 += w1; wa2 += w2; wa3 += w3; }
                *(uint32_t*)&sW[nbuf][j * PITCH + ci]     = bf2u(w0, w1);
                *(uint32_t*)&sW[nbuf][j * PITCH + ci + 2] = bf2u(w2, w3);
            }
#pragma unroll
            for (int jj = 0; jj < 2; jj++)
                *(float4*)&sT[nbuf][(tj + jj * 16) * PITCH + tc] = tr[jj];
        }
        __syncthreads();
        buf = nbuf;
    }

    if (dt == 0) {
        atomicAdd(&g_wsum[i0 + ci + 0], wa0);
        atomicAdd(&g_wsum[i0 + ci + 1], wa1);
        atomicAdd(&g_wsum[i0 + ci + 2], wa2);
        atomicAdd(&g_wsum[i0 + ci + 3], wa3);
    }

    float* numOut = (part == 0) ? g_numA : (part == 1) ? g_numB : g_numC;
    int gi = lane >> 2, gk = (lane & 3) * 2;
#pragma unroll
    for (int mb = 0; mb < 2; mb++)
#pragma unroll
        for (int nb = 0; nb < 8; nb++) {
            int i = i0 + iw + mb * 16 + gi;
            int d = d0 + dw + nb * 8 + gk;
            float* p = &numOut[(size_t)i * DD + d];
            p[0]          = acc[mb][nb][0];
            p[1]          = acc[mb][nb][1];
            p[8 * DD]     = acc[mb][nb][2];
            p[8 * DD + 1] = acc[mb][nb][3];
        }

    if (nparts == 2 && part == 0) {
        for (int idx = tid; idx < 128 * 32; idx += 256) {
            int r = idx >> 5, c4 = (idx & 31) * 4;
            *(float4*)&g_numC[(size_t)(i0 + r) * DD + d0 + c4] = make_float4(0.f, 0.f, 0.f, 0.f);
        }
    }
}

// ================= kernel 5: epilogue =================
static constexpr int EBP = 264;

__global__ void __launch_bounds__(256, 1) epi_kernel(const float* __restrict__ X,
                                                     const float* __restrict__ b_out,
                                                     const float* __restrict__ ln_s,
                                                     const float* __restrict__ ln_b,
                                                     float* __restrict__ out) {
    __shared__ __nv_bfloat16 sA[2][64 * AP];
    __shared__ __nv_bfloat16 sB[2][32 * EBP];
    __shared__ float2 red[64][2];
    __shared__ float  winv_s[64];
    __shared__ int    flag_s[64];

    int tid = threadIdx.x;
    int i0  = blockIdx.x * 64;

    if (tid < 64) {
        float ws = g_wsum[i0 + tid];
        winv_s[tid] = 1.f / (ws + EPS);
        flag_s[tid] = (ws > 0.f) ? 1 : 0;
    }
    __syncthreads();

    int ar = tid >> 2, ac = (tid & 3) * 8;
    float wv = winv_s[ar];
    int   fl = flag_s[ar];
    int wk = tid >> 3, wd = (tid & 7) * 32;

    int w = tid >> 5, lane = tid & 31;
    int iwp = (w & 3) * 16, dwp = (w >> 2) * 128;
    int q  = lane >> 3, r7 = lane & 7;
    int l15 = lane & 15, lh = (lane >> 4) * 8;

    float acc[16][4] = {};
    float4 av[2];
    uint4  wr[4];

    auto loadA = [&](int k0, float4* v) {
        size_t base = (size_t)(i0 + ar) * DD + k0 + ac;
        if (fl) {
#pragma unroll
            for (int p = 0; p < 2; p++) {
                float4 a4 = *(const float4*)&g_numA[base + p * 4];
                float4 b4 = *(const float4*)&g_numB[base + p * 4];
                float4 c4 = *(const float4*)&g_numC[base + p * 4];
                v[p] = make_float4((a4.x + b4.x + c4.x) * wv, (a4.y + b4.y + c4.y) * wv,
                                   (a4.z + b4.z + c4.z) * wv, (a4.w + b4.w + c4.w) * wv);
            }
        } else {
#pragma unroll
            for (int p = 0; p < 2; p++) v[p] = *(const float4*)&g_T[base + p * 4];
        }
    };

    loadA(0, av);
#pragma unroll
    for (int p = 0; p < 4; p++)
        wr[p] = *(const uint4*)&g_Woutb[(size_t)wk * DD + wd + p * 8];

    *(uint4*)&sA[0][ar * AP + ac] = cvt8bf(av[0], av[1]);
#pragma unroll
    for (int p = 0; p < 4; p++) *(uint4*)&sB[0][wk * EBP + wd + p * 8] = wr[p];
    __syncthreads();

    const int NCk = DD / 32;
    int buf = 0;
    for (int c = 0; c < NCk; c++) {
        int nbuf = buf ^ 1;
        if (c + 1 < NCk) {
            int k0 = (c + 1) * 32;
            loadA(k0, av);
#pragma unroll
            for (int p = 0; p < 4; p++)
                wr[p] = *(const uint4*)&g_Woutb[(size_t)(k0 + wk) * DD + wd + p * 8];
        }
        uint32_t swb = smem_u32(sA[buf]), stb = smem_u32(sB[buf]);
#pragma unroll
        for (int kk = 0; kk < 32; kk += 16) {
            uint32_t a[4];
            ldsm4(a, swb + (uint32_t)(((iwp + l15) * AP + kk + lh) * 2));
#pragma unroll
            for (int nbp = 0; nbp < 8; nbp++) {
                uint32_t b[4];
                ldsm4t(b, stb + (uint32_t)(((kk + (q & 1) * 8 + r7) * EBP + dwp + (nbp * 2 + (q >> 1)) * 8) * 2));
                mma_bf16(acc[2 * nbp],     a, b);
                mma_bf16(acc[2 * nbp + 1], a, b + 2);
            }
        }
        if (c + 1 < NCk) {
            *(uint4*)&sA[nbuf][ar * AP + ac] = cvt8bf(av[0], av[1]);
#pragma unroll
            for (int p = 0; p < 4; p++) *(uint4*)&sB[nbuf][wk * EBP + wd + p * 8] = wr[p];
        }
        __syncthreads();
        buf = nbuf;
    }

    int gi = lane >> 2, gk = (lane & 3) * 2;
    int r0 = iwp + gi, r1 = r0 + 8;
    float s0 = 0.f, q0 = 0.f, s1 = 0.f, q1 = 0.f;
#pragma unroll
    for (int nb = 0; nb < 16; nb++) {
        int d = dwp + nb * 8 + gk;
        float2 b2 = *(const float2*)&b_out[d];
        float2 x0 = *(const float2*)&X[(size_t)(i0 + r0) * DD + d];
        float2 x1 = *(const float2*)&X[(size_t)(i0 + r1) * DD + d];
        acc[nb][0] += b2.x + x0.x; acc[nb][1] += b2.y + x0.y;
        acc[nb][2] += b2.x + x1.x; acc[nb][3] += b2.y + x1.y;
        s0 += acc[nb][0] + acc[nb][1]; q0 += acc[nb][0] * acc[nb][0] + acc[nb][1] * acc[nb][1];
        s1 += acc[nb][2] + acc[nb][3]; q1 += acc[nb][2] * acc[nb][2] + acc[nb][3] * acc[nb][3];
    }
#pragma unroll
    for (int o = 1; o <= 2; o <<= 1) {
        s0 += __shfl_xor_sync(0xFFFFFFFFu, s0, o);
        q0 += __shfl_xor_sync(0xFFFFFFFFu, q0, o);
        s1 += __shfl_xor_sync(0xFFFFFFFFu, s1, o);
        q1 += __shfl_xor_sync(0xFFFFFFFFu, q1, o);
    }
    int dwi = w >> 2;
    if (gk == 0) {
        red[r0][dwi] = make_float2(s0, q0);
        red[r1][dwi] = make_float2(s1, q1);
    }
    __syncthreads();
    float2 ra0 = red[r0][0], rb0 = red[r0][1];
    float2 ra1 = red[r1][0], rb1 = red[r1][1];
    float mu0 = (ra0.x + rb0.x) * (1.f / 256.f);
    float mu1 = (ra1.x + rb1.x) * (1.f / 256.f);
    float v0  = (ra0.y + rb0.y) * (1.f / 256.f) - mu0 * mu0;
    float v1  = (ra1.y + rb1.y) * (1.f / 256.f) - mu1 * mu1;
    float rs0 = rsqrtf(v0 + LN_EPS), rs1 = rsqrtf(v1 + LN_EPS);
#pragma unroll
    for (int nb = 0; nb < 16; nb++) {
        int d = dwp + nb * 8 + gk;
        float2 ls = *(const float2*)&ln_s[d];
        float2 lb = *(const float2*)&ln_b[d];
        *(float2*)&out[(size_t)(i0 + r0) * DD + d] =
            make_float2((acc[nb][0] - mu0) * rs0 * ls.x + lb.x,
                        (acc[nb][1] - mu0) * rs0 * ls.y + lb.y);
        *(float2*)&out[(size_t)(i0 + r1) * DD + d] =
            make_float2((acc[nb][2] - mu1) * rs1 * ls.x + lb.x,
                        (acc[nb][3] - mu1) * rs1 * ls.y + lb.y);
    }
}

// ================= launch =================
extern "C" void kernel_launch(void* const* d_in, const int* in_sizes, int n_in,
                              void* d_out, int out_size) {
    const float* X     = (const float*)d_in[0];
    const float* M     = (const float*)d_in[1];
    const float* W_in  = (const float*)d_in[2];
    const float* b_in  = (const float*)d_in[3];
    const float* W_out = (const float*)d_in[4];
    const float* b_out = (const float*)d_in[5];
    const float* ln_s  = (const float*)d_in[6];
    const float* ln_b  = (const float*)d_in[7];
    float* out = (float*)d_out;

    cudaFuncSetAttribute(pre_kernel, cudaFuncAttributeMaxDynamicSharedMemorySize, PRE_SMEM);

    prep0_kernel<<<256, 256>>>(W_in, W_out);          // W -> bf16 (needed by pre's t-branch)
    pre_kernel  <<<384, 256, PRE_SMEM>>>(M, X, b_in); // colsum || T-GEMM
    prep1_kernel<<<32, 256>>>();                      // inv, wsum=0
    mma_kernel  <<<296, 256>>>(M);
    epi_kernel  <<<128, 256>>>(X, b_out, ln_s, ln_b, out);
}

// round 16
// speedup vs baseline: 1.1650x; 1.0390x over previous
#include <cuda_runtime.h>
#include <cuda_bf16.h>
#include <cstdint>

#define DI __device__ __forceinline__

static constexpr int   NN     = 8192;
static constexpr int   DD     = 256;
static constexpr float EPS    = 1e-8f;
static constexpr float THR    = 1e-6f;
static constexpr float LN_EPS = 1e-5f;

// ---------------- device scratch ----------------
__device__ float          g_part[4 * NN];
__device__ float          g_wsum[NN];
__device__ float          g_T[(size_t)NN * DD];
__device__ __nv_bfloat16  g_Tbf[(size_t)NN * DD];
__device__ __nv_bfloat16  g_Winb[DD * DD];
__device__ __nv_bfloat16  g_Woutb[DD * DD];
__device__ float          g_numA[(size_t)NN * DD];
__device__ float          g_numB[(size_t)NN * DD];
__device__ float          g_numC[(size_t)NN * DD];

// ---------------- helpers ----------------
DI uint32_t smem_u32(const void* p) {
    uint32_t a;
    asm("{ .reg .u64 t; cvta.to.shared.u64 t, %1; cvt.u32.u64 %0, t; }" : "=r"(a) : "l"(p));
    return a;
}
DI void ldsm4t(uint32_t* r, uint32_t addr) {
    asm volatile("ldmatrix.sync.aligned.m8n8.x4.trans.shared.b16 {%0,%1,%2,%3}, [%4];"
        : "=r"(r[0]), "=r"(r[1]), "=r"(r[2]), "=r"(r[3]) : "r"(addr));
}
DI void ldsm4(uint32_t* r, uint32_t addr) {
    asm volatile("ldmatrix.sync.aligned.m8n8.x4.shared.b16 {%0,%1,%2,%3}, [%4];"
        : "=r"(r[0]), "=r"(r[1]), "=r"(r[2]), "=r"(r[3]) : "r"(addr));
}
DI void mma_bf16(float* c, const uint32_t* a, const uint32_t* b) {
    asm volatile(
        "mma.sync.aligned.m16n8k16.row.col.f32.bf16.bf16.f32 "
        "{%0,%1,%2,%3}, {%4,%5,%6,%7}, {%8,%9}, {%0,%1,%2,%3};"
        : "+f"(c[0]), "+f"(c[1]), "+f"(c[2]), "+f"(c[3])
        : "r"(a[0]), "r"(a[1]), "r"(a[2]), "r"(a[3]), "r"(b[0]), "r"(b[1]));
}
DI uint32_t bf2u(float lo, float hi) {
    uint32_t r;
    asm("cvt.rn.bf16x2.f32 %0, %1, %2;" : "=r"(r) : "f"(hi), "f"(lo));
    return r;
}
DI uint4 cvt8bf(float4 a, float4 b) {
    uint4 u;
    u.x = bf2u(a.x, a.y); u.y = bf2u(a.z, a.w);
    u.z = bf2u(b.x, b.y); u.w = bf2u(b.z, b.w);
    return u;
}

// ================= kernel 1: FUSED colsum (bid<256) + T GEMM (bid>=256) =========
static constexpr int AP = 40;
static constexpr int BP = 136;
static constexpr uint32_t PRE_SMEM = 2u * 128u * AP * 2u + 2u * 32u * BP * 2u;

__global__ void __launch_bounds__(256) pre_kernel(const float* __restrict__ M,
                                                  const float* __restrict__ X,
                                                  const float* __restrict__ b_in) {
    extern __shared__ char ps[];
    int tid = threadIdx.x;

    if (blockIdx.x < 256) {
        // ---------------- colsum branch ----------------
        float* red = (float*)ps;
        int it = blockIdx.x >> 2, quart = blockIdx.x & 3;
        int i0 = it * 128;
        int rg = tid >> 5, i4 = (tid & 31) * 4;

        float a0 = 0.f, a1 = 0.f, a2 = 0.f, a3 = 0.f;
        int rbeg = quart * 2048 + rg, rend = quart * 2048 + 2048;
        for (int r = rbeg; r < rend; r += 32) {
            float4 m0 = *(const float4*)&M[(size_t)(r     ) * NN + i0 + i4];
            float4 m1 = *(const float4*)&M[(size_t)(r +  8) * NN + i0 + i4];
            float4 m2 = *(const float4*)&M[(size_t)(r + 16) * NN + i0 + i4];
            float4 m3 = *(const float4*)&M[(size_t)(r + 24) * NN + i0 + i4];
            a0 += m0.x + m1.x + m2.x + m3.x;
            a1 += m0.y + m1.y + m2.y + m3.y;
            a2 += m0.z + m1.z + m2.z + m3.z;
            a3 += m0.w + m1.w + m2.w + m3.w;
        }
        red[rg * 128 + i4 + 0] = a0; red[rg * 128 + i4 + 1] = a1;
        red[rg * 128 + i4 + 2] = a2; red[rg * 128 + i4 + 3] = a3;
        __syncthreads();
        if (tid < 128) {
            float s = 0.f;
#pragma unroll
            for (int g = 0; g < 8; g++) s += red[g * 128 + tid];
            g_part[quart * NN + i0 + tid] = s;
        }
        return;
    }

    // ---------------- T = X @ W_in + b_in branch ----------------
    int bid = blockIdx.x - 256;
    __nv_bfloat16* sA0 = (__nv_bfloat16*)ps;
    __nv_bfloat16* sA1 = sA0 + 128 * AP;
    __nv_bfloat16* sB0 = sA1 + 128 * AP;
    __nv_bfloat16* sB1 = sB0 + 32 * BP;
    __nv_bfloat16* sAb[2] = { sA0, sA1 };
    __nv_bfloat16* sBb[2] = { sB0, sB1 };

    int j0 = (bid >> 1) * 128;
    int d0 = (bid & 1) * 128;

    int xj = tid >> 1, xh = (tid & 1) * 16;
    int wk = tid >> 3, wd = (tid & 7) * 16;

    int w = tid >> 5, lane = tid & 31;
    int iw = (w & 3) * 32, dw = (w >> 2) * 64;
    int q = lane >> 3, r7 = lane & 7;
    int l15 = lane & 15, lh = (lane >> 4) * 8;

    float acc[2][8][4] = {};
    float4 xr[4];
    uint4  wr[2];

#pragma unroll
    for (int p = 0; p < 4; p++)
        xr[p] = *(const float4*)&X[(size_t)(j0 + xj) * DD + xh + p * 4];
#pragma unroll
    for (int p = 0; p < 2; p++)
        wr[p] = *(const uint4*)&g_Winb[(size_t)wk * DD + d0 + wd + p * 8];

    *(uint4*)&sAb[0][xj * AP + xh]     = cvt8bf(xr[0], xr[1]);
    *(uint4*)&sAb[0][xj * AP + xh + 8] = cvt8bf(xr[2], xr[3]);
    *(uint4*)&sBb[0][wk * BP + wd]     = wr[0];
    *(uint4*)&sBb[0][wk * BP + wd + 8] = wr[1];
    __syncthreads();

    const int NCk = DD / 32;
    int buf = 0;
    for (int c = 0; c < NCk; c++) {
        int nbuf = buf ^ 1;
        if (c + 1 < NCk) {
            int k0 = (c + 1) * 32;
#pragma unroll
            for (int p = 0; p < 4; p++)
                xr[p] = *(const float4*)&X[(size_t)(j0 + xj) * DD + k0 + xh + p * 4];
#pragma unroll
            for (int p = 0; p < 2; p++)
                wr[p] = *(const uint4*)&g_Winb[(size_t)(k0 + wk) * DD + d0 + wd + p * 8];
        }
        uint32_t swb = smem_u32(sAb[buf]), stb = smem_u32(sBb[buf]);
#pragma unroll
        for (int kk = 0; kk < 32; kk += 16) {
            uint32_t a[2][4];
#pragma unroll
            for (int mb = 0; mb < 2; mb++)
                ldsm4(a[mb], swb + (uint32_t)(((iw + mb * 16 + l15) * AP + kk + lh) * 2));
#pragma unroll
            for (int nbp = 0; nbp < 4; nbp++) {
                uint32_t b[4];
                ldsm4t(b, stb + (uint32_t)(((kk + (q & 1) * 8 + r7) * BP + dw + (nbp * 2 + (q >> 1)) * 8) * 2));
                mma_bf16(acc[0][2 * nbp],     a[0], b);
                mma_bf16(acc[1][2 * nbp],     a[1], b);
                mma_bf16(acc[0][2 * nbp + 1], a[0], b + 2);
                mma_bf16(acc[1][2 * nbp + 1], a[1], b + 2);
            }
        }
        if (c + 1 < NCk) {
            *(uint4*)&sAb[nbuf][xj * AP + xh]     = cvt8bf(xr[0], xr[1]);
            *(uint4*)&sAb[nbuf][xj * AP + xh + 8] = cvt8bf(xr[2], xr[3]);
            *(uint4*)&sBb[nbuf][wk * BP + wd]     = wr[0];
            *(uint4*)&sBb[nbuf][wk * BP + wd + 8] = wr[1];
        }
        __syncthreads();
        buf = nbuf;
    }

    int gi = lane >> 2, gk = (lane & 3) * 2;
#pragma unroll
    for (int mb = 0; mb < 2; mb++)
#pragma unroll
        for (int nb = 0; nb < 8; nb++) {
            int dg = d0 + dw + nb * 8 + gk;
            float2 b2 = *(const float2*)&b_in[dg];
            float v0 = acc[mb][nb][0] + b2.x, v1 = acc[mb][nb][1] + b2.y;
            float v2 = acc[mb][nb][2] + b2.x, v3 = acc[mb][nb][3] + b2.y;
            size_t r0 = (size_t)(j0 + iw + mb * 16 + gi) * DD + dg;
            *(float2*)&g_T[r0]          = make_float2(v0, v1);
            *(float2*)&g_T[r0 + 8 * DD] = make_float2(v2, v3);
            *(uint32_t*)&g_Tbf[r0]          = bf2u(v0, v1);
            *(uint32_t*)&g_Tbf[r0 + 8 * DD] = bf2u(v2, v3);
        }
}

// ================= kernel 0: prep0 — W -> bf16, wsum=0 =================
__global__ void prep0_kernel(const float* __restrict__ W_in,
                             const float* __restrict__ W_out) {
    int gid = blockIdx.x * 256 + threadIdx.x;
    if (gid < NN) g_wsum[gid] = 0.f;
    g_Winb[gid]  = __float2bfloat16(W_in[gid]);
    g_Woutb[gid] = __float2bfloat16(W_out[gid]);
}

// ================= kernel 4: big GEMM (296 CTAs, 2/SM; inv computed locally) ====
static constexpr int PITCH = 136;

__global__ void __launch_bounds__(256, 2) mma_kernel(const float* __restrict__ M) {
    __shared__ __nv_bfloat16 sW[2][32 * PITCH];
    __shared__ __nv_bfloat16 sT[2][32 * PITCH];

    int tid = threadIdx.x;
    int bid = blockIdx.x;
    int tile, part, nparts, cbeg, NC;
    if (bid < 120) {
        tile = bid / 3; part = bid % 3; nparts = 3;
        cbeg = (part == 0) ? 0 : (86 + 85 * (part - 1));
        NC   = (part == 0) ? 86 : 85;
    } else {
        int b2 = bid - 120;
        tile = 40 + (b2 >> 1); part = b2 & 1; nparts = 2;
        cbeg = part * 128; NC = 128;
    }
    int it = tile >> 1, dt = tile & 1;
    int i0 = it * 128, d0 = dt * 128;

    int cj = tid >> 5;
    int ci = (tid & 31) * 4;
    // compute inv locally from colsum partials (removes prep1 launch)
    float4 inv4;
    {
        float s[4];
#pragma unroll
        for (int p = 0; p < 4; p++) {
            int i = i0 + ci + p;
            s[p] = g_part[i] + g_part[NN + i] + g_part[2 * NN + i] + g_part[3 * NN + i];
        }
        inv4 = make_float4(1.f / (s[0] + EPS), 1.f / (s[1] + EPS),
                           1.f / (s[2] + EPS), 1.f / (s[3] + EPS));
    }
    float wa0 = 0.f, wa1 = 0.f, wa2 = 0.f, wa3 = 0.f;

    int tj = tid >> 4;
    int tc = (tid & 15) * 8;

    int w = tid >> 5, lane = tid & 31;
    int iw = (w & 3) * 32, dw = (w >> 2) * 64;
    int q  = lane >> 3, r7 = lane & 7;

    float acc[2][8][4] = {};

    const float*          Mb = M     + (size_t)cbeg * 32 * NN;
    const __nv_bfloat16*  Tb = g_Tbf + (size_t)cbeg * 32 * DD;

    float4 mr[4], tr[2];
#pragma unroll
    for (int jj = 0; jj < 4; jj++)
        mr[jj] = *(const float4*)&Mb[(size_t)(cj + jj * 8) * NN + i0 + ci];
#pragma unroll
    for (int jj = 0; jj < 2; jj++)
        tr[jj] = *(const float4*)&Tb[(size_t)(tj + jj * 16) * DD + d0 + tc];

#pragma unroll
    for (int jj = 0; jj < 4; jj++) {
        int j = cj + jj * 8;
        float w0 = mr[jj].x * inv4.x; w0 = (w0 > THR) ? w0 : 0.f;
        float w1 = mr[jj].y * inv4.y; w1 = (w1 > THR) ? w1 : 0.f;
        float w2 = mr[jj].z * inv4.z; w2 = (w2 > THR) ? w2 : 0.f;
        float w3 = mr[jj].w * inv4.w; w3 = (w3 > THR) ? w3 : 0.f;
        if (dt == 0) { wa0 += w0; wa1 += w1; wa2 += w2; wa3 += w3; }
        *(uint32_t*)&sW[0][j * PITCH + ci]     = bf2u(w0, w1);
        *(uint32_t*)&sW[0][j * PITCH + ci + 2] = bf2u(w2, w3);
    }
#pragma unroll
    for (int jj = 0; jj < 2; jj++)
        *(float4*)&sT[0][(tj + jj * 16) * PITCH + tc] = tr[jj];
    __syncthreads();

    int buf = 0;
    for (int c = 0; c < NC; c++) {
        int nbuf = buf ^ 1;
        if (c + 1 < NC) {
            size_t koff = (size_t)(c + 1) * 32;
#pragma unroll
            for (int jj = 0; jj < 4; jj++)
                mr[jj] = *(const float4*)&Mb[(koff + cj + jj * 8) * NN + i0 + ci];
#pragma unroll
            for (int jj = 0; jj < 2; jj++)
                tr[jj] = *(const float4*)&Tb[(koff + tj + jj * 16) * DD + d0 + tc];
        }

        uint32_t swb = smem_u32(sW[buf]), stb = smem_u32(sT[buf]);
#pragma unroll
        for (int kk = 0; kk < 32; kk += 16) {
            uint32_t a[2][4];
#pragma unroll
            for (int mb = 0; mb < 2; mb++)
                ldsm4t(a[mb], swb + (uint32_t)(((kk + (q >> 1) * 8 + r7) * PITCH + iw + mb * 16 + (q & 1) * 8) * 2));
#pragma unroll
            for (int nbp = 0; nbp < 4; nbp++) {
                uint32_t b[4];
                ldsm4t(b, stb + (uint32_t)(((kk + (q & 1) * 8 + r7) * PITCH + dw + (nbp * 2 + (q >> 1)) * 8) * 2));
                mma_bf16(acc[0][2 * nbp],     a[0], b);
                mma_bf16(acc[1][2 * nbp],     a[1], b);
                mma_bf16(acc[0][2 * nbp + 1], a[0], b + 2);
                mma_bf16(acc[1][2 * nbp + 1], a[1], b + 2);
            }
        }

        if (c + 1 < NC) {
#pragma unroll
            for (int jj = 0; jj < 4; jj++) {
                int j = cj + jj * 8;
                float w0 = mr[jj].x * inv4.x; w0 = (w0 > THR) ? w0 : 0.f;
                float w1 = mr[jj].y * inv4.y; w1 = (w1 > THR) ? w1 : 0.f;
                float w2 = mr[jj].z * inv4.z; w2 = (w2 > THR) ? w2 : 0.f;
                float w3 = mr[jj].w * inv4.w; w3 = (w3 > THR) ? w3 : 0.f;
                if (dt == 0) { wa0 += w0; wa1 += w1; wa2 += w2; wa3 += w3; }
                *(uint32_t*)&sW[nbuf][j * PITCH + ci]     = bf2u(w0, w1);
                *(uint32_t*)&sW[nbuf][j * PITCH + ci + 2] = bf2u(w2, w3);
            }
#pragma unroll
            for (int jj = 0; jj < 2; jj++)
                *(float4*)&sT[nbuf][(tj + jj * 16) * PITCH + tc] = tr[jj];
        }
        __syncthreads();
        buf = nbuf;
    }

    if (dt == 0) {
        atomicAdd(&g_wsum[i0 + ci + 0], wa0);
        atomicAdd(&g_wsum[i0 + ci + 1], wa1);
        atomicAdd(&g_wsum[i0 + ci + 2], wa2);
        atomicAdd(&g_wsum[i0 + ci + 3], wa3);
    }

    float* numOut = (part == 0) ? g_numA : (part == 1) ? g_numB : g_numC;
    int gi = lane >> 2, gk = (lane & 3) * 2;
#pragma unroll
    for (int mb = 0; mb < 2; mb++)
#pragma unroll
        for (int nb = 0; nb < 8; nb++) {
            int i = i0 + iw + mb * 16 + gi;
            int d = d0 + dw + nb * 8 + gk;
            float* p = &numOut[(size_t)i * DD + d];
            p[0]          = acc[mb][nb][0];
            p[1]          = acc[mb][nb][1];
            p[8 * DD]     = acc[mb][nb][2];
            p[8 * DD + 1] = acc[mb][nb][3];
        }
    // NOTE: no g_numC zero-fill — epi only reads C for global rows < 2560
}

// ================= kernel 5: epilogue (256 CTAs x 32 rows, occ 2) =================
static constexpr int EBP = 264;

__global__ void __launch_bounds__(256, 2) epi_kernel(const float* __restrict__ X,
                                                     const float* __restrict__ b_out,
                                                     const float* __restrict__ ln_s,
                                                     const float* __restrict__ ln_b,
                                                     float* __restrict__ out) {
    __shared__ __nv_bfloat16 sA[2][32 * AP];
    __shared__ __nv_bfloat16 sB[2][32 * EBP];
    __shared__ float2 red[32][4];
    __shared__ float  winv_s[32];
    __shared__ int    flag_s[32];

    int tid = threadIdx.x;
    int i0  = blockIdx.x * 32;
    bool three = (i0 < 2560);          // rows of 3-part k-split tiles

    if (tid < 32) {
        float ws = g_wsum[i0 + tid];
        winv_s[tid] = 1.f / (ws + EPS);
        flag_s[tid] = (ws > 0.f) ? 1 : 0;
    }
    __syncthreads();

    // A producer: thread -> (row ar 0..31, 4-col group ac)
    int ar = tid >> 3, ac = (tid & 7) * 4;
    float wv = winv_s[ar];
    int   fl = flag_s[ar];
    // B producer: thread -> (k row wk 0..31, 32-col group wd)
    int wk = tid >> 3, wd = (tid & 7) * 32;

    int w = tid >> 5, lane = tid & 31;
    int iwp = (w & 1) * 16, dwp = (w >> 1) * 64;
    int q  = lane >> 3, r7 = lane & 7;
    int l15 = lane & 15, lh = (lane >> 4) * 8;

    float acc[8][4] = {};
    float4 av;
    uint4  wr[4];

    auto loadA = [&](int k0) {
        size_t base = (size_t)(i0 + ar) * DD + k0 + ac;
        if (fl) {
            float4 a4 = *(const float4*)&g_numA[base];
            float4 b4 = *(const float4*)&g_numB[base];
            float s0 = a4.x + b4.x, s1 = a4.y + b4.y, s2 = a4.z + b4.z, s3 = a4.w + b4.w;
            if (three) {
                float4 c4 = *(const float4*)&g_numC[base];
                s0 += c4.x; s1 += c4.y; s2 += c4.z; s3 += c4.w;
            }
            av = make_float4(s0 * wv, s1 * wv, s2 * wv, s3 * wv);
        } else {
            av = *(const float4*)&g_T[base];
        }
    };

    loadA(0);
#pragma unroll
    for (int p = 0; p < 4; p++)
        wr[p] = *(const uint4*)&g_Woutb[(size_t)wk * DD + wd + p * 8];

    {
        uint2 u; u.x = bf2u(av.x, av.y); u.y = bf2u(av.z, av.w);
        *(uint2*)&sA[0][ar * AP + ac] = u;
#pragma unroll
        for (int p = 0; p < 4; p++) *(uint4*)&sB[0][wk * EBP + wd + p * 8] = wr[p];
    }
    __syncthreads();

    const int NCk = DD / 32;
    int buf = 0;
    for (int c = 0; c < NCk; c++) {
        int nbuf = buf ^ 1;
        if (c + 1 < NCk) {
            int k0 = (c + 1) * 32;
            loadA(k0);
#pragma unroll
            for (int p = 0; p < 4; p++)
                wr[p] = *(const uint4*)&g_Woutb[(size_t)(k0 + wk) * DD + wd + p * 8];
        }
        uint32_t swb = smem_u32(sA[buf]), stb = smem_u32(sB[buf]);
#pragma unroll
        for (int kk = 0; kk < 32; kk += 16) {
            uint32_t a[4];
            ldsm4(a, swb + (uint32_t)(((iwp + l15) * AP + kk + lh) * 2));
#pragma unroll
            for (int nbp = 0; nbp < 4; nbp++) {
                uint32_t b[4];
                ldsm4t(b, stb + (uint32_t)(((kk + (q & 1) * 8 + r7) * EBP + dwp + (nbp * 2 + (q >> 1)) * 8) * 2));
                mma_bf16(acc[2 * nbp],     a, b);
                mma_bf16(acc[2 * nbp + 1], a, b + 2);
            }
        }
        if (c + 1 < NCk) {
            uint2 u; u.x = bf2u(av.x, av.y); u.y = bf2u(av.z, av.w);
            *(uint2*)&sA[nbuf][ar * AP + ac] = u;
#pragma unroll
            for (int p = 0; p < 4; p++) *(uint4*)&sB[nbuf][wk * EBP + wd + p * 8] = wr[p];
        }
        __syncthreads();
        buf = nbuf;
    }

    // ---- + b_out + X, then LayerNorm ----
    int gi = lane >> 2, gk = (lane & 3) * 2;
    int r0 = iwp + gi, r1 = r0 + 8;
    float s0 = 0.f, q0 = 0.f, s1 = 0.f, q1 = 0.f;
#pragma unroll
    for (int nb = 0; nb < 8; nb++) {
        int d = dwp + nb * 8 + gk;
        float2 b2 = *(const float2*)&b_out[d];
        float2 x0 = *(const float2*)&X[(size_t)(i0 + r0) * DD + d];
        float2 x1 = *(const float2*)&X[(size_t)(i0 + r1) * DD + d];
        acc[nb][0] += b2.x + x0.x; acc[nb][1] += b2.y + x0.y;
        acc[nb][2] += b2.x + x1.x; acc[nb][3] += b2.y + x1.y;
        s0 += acc[nb][0] + acc[nb][1]; q0 += acc[nb][0] * acc[nb][0] + acc[nb][1] * acc[nb][1];
        s1 += acc[nb][2] + acc[nb][3]; q1 += acc[nb][2] * acc[nb][2] + acc[nb][3] * acc[nb][3];
    }
#pragma unroll
    for (int o = 1; o <= 2; o <<= 1) {
        s0 += __shfl_xor_sync(0xFFFFFFFFu, s0, o);
        q0 += __shfl_xor_sync(0xFFFFFFFFu, q0, o);
        s1 += __shfl_xor_sync(0xFFFFFFFFu, s1, o);
        q1 += __shfl_xor_sync(0xFFFFFFFFu, q1, o);
    }
    int dwi = w >> 1;
    if (gk == 0) {
        red[r0][dwi] = make_float2(s0, q0);
        red[r1][dwi] = make_float2(s1, q1);
    }
    __syncthreads();
    float sm0 = 0.f, sq0 = 0.f, sm1 = 0.f, sq1 = 0.f;
#pragma unroll
    for (int p = 0; p < 4; p++) {
        float2 e0 = red[r0][p], e1 = red[r1][p];
        sm0 += e0.x; sq0 += e0.y;
        sm1 += e1.x; sq1 += e1.y;
    }
    float mu0 = sm0 * (1.f / 256.f);
    float mu1 = sm1 * (1.f / 256.f);
    float v0  = sq0 * (1.f / 256.f) - mu0 * mu0;
    float v1  = sq1 * (1.f / 256.f) - mu1 * mu1;
    float rs0 = rsqrtf(v0 + LN_EPS), rs1 = rsqrtf(v1 + LN_EPS);
#pragma unroll
    for (int nb = 0; nb < 8; nb++) {
        int d = dwp + nb * 8 + gk;
        float2 ls = *(const float2*)&ln_s[d];
        float2 lb = *(const float2*)&ln_b[d];
        *(float2*)&out[(size_t)(i0 + r0) * DD + d] =
            make_float2((acc[nb][0] - mu0) * rs0 * ls.x + lb.x,
                        (acc[nb][1] - mu0) * rs0 * ls.y + lb.y);
        *(float2*)&out[(size_t)(i0 + r1) * DD + d] =
            make_float2((acc[nb][2] - mu1) * rs1 * ls.x + lb.x,
                        (acc[nb][3] - mu1) * rs1 * ls.y + lb.y);
    }
}

// ================= launch =================
extern "C" void kernel_launch(void* const* d_in, const int* in_sizes, int n_in,
                              void* d_out, int out_size) {
    const float* X     = (const float*)d_in[0];
    const float* M     = (const float*)d_in[1];
    const float* W_in  = (const float*)d_in[2];
    const float* b_in  = (const float*)d_in[3];
    const float* W_out = (const float*)d_in[4];
    const float* b_out = (const float*)d_in[5];
    const float* ln_s  = (const float*)d_in[6];
    const float* ln_b  = (const float*)d_in[7];
    float* out = (float*)d_out;

    cudaFuncSetAttribute(pre_kernel, cudaFuncAttributeMaxDynamicSharedMemorySize, PRE_SMEM);

    prep0_kernel<<<256, 256>>>(W_in, W_out);          // W -> bf16, wsum=0
    pre_kernel  <<<384, 256, PRE_SMEM>>>(M, X, b_in); // colsum || T-GEMM
    mma_kernel  <<<296, 256>>>(M);                    // inv computed in-kernel
    epi_kernel  <<<256, 256>>>(X, b_out, ln_s, ln_b, out);
}